// round 15
// baseline (speedup 1.0000x reference)
#include <cuda_runtime.h>
#include <cuda_fp16.h>
#include <cstdint>

typedef uint32_t u32;
typedef unsigned long long u64t;

#define N_TOK 1024
#define TZ 128
#define TD 64
#define NB 38
#define EPSF 1e-5f
#define TM 128
#define THREADS 512
#define NBLOCKS 152
#define NTILES ((N_TOK * N_TOK) / TM)   // 8192

// strides — conflict-free fragment access
#define ZSTR 136      // f32 units; ≡8 mod 32
#define VNSTR 36      // u32 half2 units; ≡4 mod 32
#define W1PSTR 68     // u64 units; ≡4 mod 16 -> LDS.64 conflict-free
#define W2PSTR 132    // u64 units; ≡4 mod 16

// smem offsets (4-byte units)
#define ZA0_F 0                         // z f32 buf0: 128*136 = 17408
#define ZA1_F (TM * ZSTR)               // 17408
#define VN0_F (2 * TM * ZSTR)           // 34816
#define VN1_F (VN0_F + TM * VNSTR)      // 39424
#define W1P_F (VN1_F + TM * VNSTR)      // 44032 (8B aligned): 32 rows x 68 u64
#define W2P_F (W1P_F + 32 * W1PSTR * 2) // 48384 (8B aligned): 16 rows x 132 u64
#define WAS_F (W2P_F + 16 * W2PSTR * 2) // 52608
#define S_F   (WAS_F + NB * TD)
#define T_F   (S_F + TD)
#define VG_F  (T_F + TD)
#define VB_F  (VG_F + TD)
#define SMEM_FLOATS (VB_F + TD)         // 55296 * 4B = 221184 B

// ---------------- helpers ----------------
__device__ __forceinline__ u32 packh2(float lo, float hi) {
    half2 h = __floats2half2_rn(lo, hi);      // .x = lo (low 16 bits)
    return *(u32*)&h;
}
__device__ __forceinline__ void cpa16(float* dst, const void* g) {
    u32 a = (u32)__cvta_generic_to_shared(dst);
    asm volatile("cp.async.cg.shared.global [%0], [%1], 16;" :: "r"(a), "l"(g));
}
__device__ __forceinline__ void cpa_commit() { asm volatile("cp.async.commit_group;"); }
__device__ __forceinline__ void cpa_wait0() { asm volatile("cp.async.wait_group 0;" ::: "memory"); }

// D += A(16x16,row) * B(16x8,col), fp16 inputs, f32 accum
__device__ __forceinline__ void mma16(float* c, const u32* a, u32 b0, u32 b1) {
    asm volatile(
        "mma.sync.aligned.m16n8k16.row.col.f32.f16.f16.f32 "
        "{%0,%1,%2,%3}, {%4,%5,%6,%7}, {%8,%9}, {%0,%1,%2,%3};"
        : "+f"(c[0]), "+f"(c[1]), "+f"(c[2]), "+f"(c[3])
        : "r"(a[0]), "r"(a[1]), "r"(a[2]), "r"(a[3]), "r"(b0), "r"(b1));
}

// ---------------- main fused kernel ----------------
__global__ __launch_bounds__(THREADS, 1)
void td_kernel(const float* __restrict__ z, const float* __restrict__ cc,
               const float* __restrict__ tdm, const float* __restrict__ Wz,
               const float* __restrict__ Wa, const float* __restrict__ Wu,
               const float* __restrict__ zg, const float* __restrict__ zb,
               const float* __restrict__ vg, const float* __restrict__ vb,
               float* __restrict__ out)
{
    extern __shared__ float smf[];
    u32* smu = (u32*)smf;
    u64t* w1p = (u64t*)&smu[W1P_F];
    u64t* w2p = (u64t*)&smu[W2P_F];
    const int t = threadIdx.x;
    const int wid = t >> 5, lane = t & 31;
    const int g = lane >> 2, tg = lane & 3;
    const bool isG1 = (wid < 8);
    const int R1 = (wid & 7) * 16;
    const int t2 = t & 255;

    // ---- prefetch first tile (all 512 threads) ----
    const int tile0 = blockIdx.x;
    {
        const float* src = z + (size_t)tile0 * TM * TZ;
        #pragma unroll
        for (int i = 0; i < 8; i++) {
            int e = i * THREADS + t;            // 0..4095 float4
            cpa16(&smf[ZA0_F + (e >> 5) * ZSTR + (e & 31) * 4], src + e * 4);
        }
        cpa_commit();
    }

    // ---- one-time weight staging (paired u64: {kp, kp+4} halves) ----
    // W1P[row= ks*4+tg][n]: lo = half2 of k-pair kp=8ks+tg, hi = kp+4
    for (int s = t; s < 32 * TD; s += THREADS) {
        int row = s >> 6, n = s & 63;
        int kp = 8 * (row >> 2) + (row & 3);
        u32 lo = packh2(Wz[n * TZ + 2 * kp] * zg[2 * kp],
                        Wz[n * TZ + 2 * kp + 1] * zg[2 * kp + 1]);
        int kq = kp + 4;
        u32 hi = packh2(Wz[n * TZ + 2 * kq] * zg[2 * kq],
                        Wz[n * TZ + 2 * kq + 1] * zg[2 * kq + 1]);
        w1p[row * W1PSTR + n] = ((u64t)hi << 32) | lo;
    }
    // W2P[row= ks*4+tg][c]: lo = half2 of d-pair kp=8ks+tg, hi = kp+4
    for (int s = t; s < 16 * TZ; s += THREADS) {
        int row = s >> 7, c = s & 127;
        int kp = 8 * (row >> 2) + (row & 3);
        u32 lo = packh2(Wu[c * TD + 2 * kp], Wu[c * TD + 2 * kp + 1]);
        int kq = kp + 4;
        u32 hi = packh2(Wu[c * TD + 2 * kq], Wu[c * TD + 2 * kq + 1]);
        w2p[row * W2PSTR + c] = ((u64t)hi << 32) | lo;
    }
    for (int s = t; s < NB * TD; s += THREADS) {
        int k = s >> 6, d = s & 63;
        smf[WAS_F + k * TD + d] = Wa[d * NB + k];
    }
    if (t < TD) {
        float S = 0.f, T = 0.f;
        for (int k = 0; k < TZ; k++) {
            S += __half2float(__float2half_rn(Wz[t * TZ + k] * zg[k]));
            T += Wz[t * TZ + k] * zb[k];
        }
        smf[S_F + t] = S; smf[T_F + t] = T;
        smf[VG_F + t] = vg[t]; smf[VB_F + t] = vb[t];
    }

    const int ng1 = (NTILES - 1 - tile0) / NBLOCKS + 1;
    const int it_count = ng1 + 1;        // +1 drain iteration

    int tile = tile0;
    for (int it = 0; it < it_count; it++, tile += NBLOCKS) {
        const int cur = it & 1;
        float* zc   = &smf[cur ? ZA1_F : ZA0_F];       // z(tile)            [G1 in]
        u32* vncur  = &smu[cur ? VN1_F : VN0_F];       // vn(tile)           [G1 out]
        u32* vnprev = &smu[cur ? VN0_F : VN1_F];       // vn(tile-NBLOCKS)   [G2 in]
        float* znxt = &smf[cur ? ZA0_F : ZA1_F];       // z(tile+NBLOCKS)    [prefetch dst]

        cpa_wait0();
        __syncthreads();   // single block barrier per iteration

        if (isG1) {
            if (tile < NTILES) {
                const int base_p = tile * TM;

                // ---- bins + mask (rows R1+g, R1+g+8) ----
                int bin0, bin1;
                float mk0, mk1;
                {
                    const int i0 = base_p >> 10;
                    const int jb = base_p & (N_TOK - 1);
                    const float cx = __ldg(cc + i0 * 3 + 0);
                    const float cy = __ldg(cc + i0 * 3 + 1);
                    const float cz = __ldg(cc + i0 * 3 + 2);
                    #pragma unroll
                    for (int i = 0; i < 2; i++) {
                        const int row = R1 + g + 8 * i;
                        const int j0 = jb + row;
                        float dx = cx - __ldg(cc + j0 * 3 + 0);
                        float dy = cy - __ldg(cc + j0 * 3 + 1);
                        float dz = cz - __ldg(cc + j0 * 3 + 2);
                        float dist = sqrtf(dx * dx + dy * dy + dz * dz);
                        int idx = 0;
                        #pragma unroll
                        for (int k = 0; k < NB - 1; k++) {
                            float b = (float)(3.25 + k * (47.5 / 36.0));
                            idx += (dist > b) ? 1 : 0;
                        }
                        if (i == 0) { bin0 = idx; mk0 = __ldg(tdm + base_p + row); }
                        else        { bin1 = idx; mk1 = __ldg(tdm + base_p + row); }
                    }
                }

                // ---- GEMM1 fp16 (warp tile 16x64, 8 k16-steps) + LN1 stats ----
                float acc[8][4];
                #pragma unroll
                for (int b = 0; b < 8; b++)
                    #pragma unroll
                    for (int cI = 0; cI < 4; cI++) acc[b][cI] = 0.f;
                float s0 = 0.f, q0 = 0.f, s1 = 0.f, q1 = 0.f;

                #pragma unroll
                for (int ks = 0; ks < 8; ks++) {
                    const int k0 = ks * 16;
                    const float* zr = &zc[(R1 + g) * ZSTR + k0 + 2 * tg];
                    float2 p0 = *(const float2*)zr;
                    float2 p2 = *(const float2*)(zr + 8);
                    float2 p1 = *(const float2*)(zr + 8 * ZSTR);
                    float2 p3 = *(const float2*)(zr + 8 * ZSTR + 8);
                    s0 += p0.x + p0.y + p2.x + p2.y;
                    q0 += p0.x * p0.x + p0.y * p0.y + p2.x * p2.x + p2.y * p2.y;
                    s1 += p1.x + p1.y + p3.x + p3.y;
                    q1 += p1.x * p1.x + p1.y * p1.y + p3.x * p3.x + p3.y * p3.y;
                    u32 afr[4];
                    afr[0] = packh2(p0.x, p0.y);
                    afr[1] = packh2(p1.x, p1.y);
                    afr[2] = packh2(p2.x, p2.y);
                    afr[3] = packh2(p3.x, p3.y);
                    const u64t* wb = &w1p[(4 * ks + tg) * W1PSTR + g];
                    #pragma unroll
                    for (int nt = 0; nt < 8; nt++) {
                        u64t w = wb[8 * nt];
                        mma16(acc[nt], afr, (u32)w, (u32)(w >> 32));
                    }
                }

                // LN1 finalize (reduce over tg lanes)
                float m1a, r1a, m1b, r1b;
                {
                    float sa = s0, qa = q0, sb = s1, qb = q1;
                    sa += __shfl_xor_sync(0xffffffffu, sa, 1);
                    qa += __shfl_xor_sync(0xffffffffu, qa, 1);
                    sb += __shfl_xor_sync(0xffffffffu, sb, 1);
                    qb += __shfl_xor_sync(0xffffffffu, qb, 1);
                    sa += __shfl_xor_sync(0xffffffffu, sa, 2);
                    qa += __shfl_xor_sync(0xffffffffu, qa, 2);
                    sb += __shfl_xor_sync(0xffffffffu, sb, 2);
                    qb += __shfl_xor_sync(0xffffffffu, qb, 2);
                    m1a = sa * (1.f / TZ);
                    float va = fmaxf(qa * (1.f / TZ) - m1a * m1a, 0.f);
                    r1a = rsqrtf(va + EPSF);
                    m1b = sb * (1.f / TZ);
                    float vb_ = fmaxf(qb * (1.f / TZ) - m1b * m1b, 0.f);
                    r1b = rsqrtf(vb_ + EPSF);
                }

                // ---- epilogue 1: LN1-fold + bin column + LN2 stats (warp-local) ----
                float s2a = 0.f, q2a = 0.f, s2b = 0.f, q2b = 0.f;
                #pragma unroll
                for (int nt = 0; nt < 8; nt++) {
                    const int col = 8 * nt + 2 * tg;
                    float2 Sv = *(const float2*)&smf[S_F + col];
                    float2 Tv = *(const float2*)&smf[T_F + col];
                    float2 W0 = *(const float2*)&smf[WAS_F + bin0 * TD + col];
                    float2 W1v = *(const float2*)&smf[WAS_F + bin1 * TD + col];
                    float v0 = r1a * (acc[nt][0] - m1a * Sv.x) + Tv.x + mk0 * W0.x;
                    float v1 = r1a * (acc[nt][1] - m1a * Sv.y) + Tv.y + mk0 * W0.y;
                    float v2 = r1b * (acc[nt][2] - m1b * Sv.x) + Tv.x + mk1 * W1v.x;
                    float v3 = r1b * (acc[nt][3] - m1b * Sv.y) + Tv.y + mk1 * W1v.y;
                    acc[nt][0] = v0; acc[nt][1] = v1; acc[nt][2] = v2; acc[nt][3] = v3;
                    s2a += v0 + v1;  q2a += v0 * v0 + v1 * v1;
                    s2b += v2 + v3;  q2b += v2 * v2 + v3 * v3;
                }
                s2a += __shfl_xor_sync(0xffffffffu, s2a, 1);
                q2a += __shfl_xor_sync(0xffffffffu, q2a, 1);
                s2b += __shfl_xor_sync(0xffffffffu, s2b, 1);
                q2b += __shfl_xor_sync(0xffffffffu, q2b, 1);
                s2a += __shfl_xor_sync(0xffffffffu, s2a, 2);
                q2a += __shfl_xor_sync(0xffffffffu, q2a, 2);
                s2b += __shfl_xor_sync(0xffffffffu, s2b, 2);
                q2b += __shfl_xor_sync(0xffffffffu, q2b, 2);
                float m2a = s2a * (1.f / TD);
                float vva = fmaxf(q2a * (1.f / TD) - m2a * m2a, 0.f);
                float sca = 2.f * rsqrtf(4.f * vva + EPSF);    // exact v+v doubling
                float m2b = s2b * (1.f / TD);
                float vvb = fmaxf(q2b * (1.f / TD) - m2b * m2b, 0.f);
                float scb = 2.f * rsqrtf(4.f * vvb + EPSF);

                // ---- normalize + relu -> vn (half2 packed along d) ----
                #pragma unroll
                for (int nt = 0; nt < 8; nt++) {
                    const int col = 8 * nt + 2 * tg;
                    float2 gv = *(const float2*)&smf[VG_F + col];
                    float2 bv = *(const float2*)&smf[VB_F + col];
                    float a0 = fmaxf(fmaf((acc[nt][0] - m2a) * sca, gv.x, bv.x), 0.f);
                    float a1 = fmaxf(fmaf((acc[nt][1] - m2a) * sca, gv.y, bv.y), 0.f);
                    float b0 = fmaxf(fmaf((acc[nt][2] - m2b) * scb, gv.x, bv.x), 0.f);
                    float b1 = fmaxf(fmaf((acc[nt][3] - m2b) * scb, gv.y, bv.y), 0.f);
                    const int kp = 4 * nt + tg;
                    vncur[(R1 + g) * VNSTR + kp]     = packh2(a0, a1);
                    vncur[(R1 + g + 8) * VNSTR + kp] = packh2(b0, b1);
                }
            }
        } else {
            // ---- prefetch next z first (max overlap), then GEMM2 ----
            const int tile_next = tile + NBLOCKS;
            if (tile_next < NTILES) {
                const float* src = z + (size_t)tile_next * TM * TZ;
                #pragma unroll
                for (int i = 0; i < 16; i++) {
                    int e = i * 256 + t2;
                    cpa16(&znxt[(e >> 5) * ZSTR + (e & 31) * 4], src + e * 4);
                }
                cpa_commit();
            }

            // ---- GEMM2 fp16 (warp tile 16x128, 4 k16-steps) on vn(tile-NBLOCKS) ----
            if (it > 0) {
                const int base_p = (tile - NBLOCKS) * TM;
                float acc2[16][4];
                #pragma unroll
                for (int b = 0; b < 16; b++)
                    #pragma unroll
                    for (int cI = 0; cI < 4; cI++) acc2[b][cI] = 0.f;

                #pragma unroll
                for (int ks = 0; ks < 4; ks++) {
                    const u32* vr = &vnprev[(R1 + g) * VNSTR + 8 * ks + tg];
                    u32 afr[4];
                    afr[0] = vr[0];
                    afr[1] = vr[8 * VNSTR];
                    afr[2] = vr[4];
                    afr[3] = vr[8 * VNSTR + 4];
                    const u64t* wb = &w2p[(4 * ks + tg) * W2PSTR + g];
                    #pragma unroll
                    for (int nt = 0; nt < 16; nt++) {
                        u64t w = wb[8 * nt];
                        mma16(acc2[nt], afr, (u32)w, (u32)(w >> 32));
                    }
                }
                {
                    const int ra = base_p + R1 + g;
                    #pragma unroll
                    for (int nt = 0; nt < 16; nt++) {
                        const int col = 8 * nt + 2 * tg;
                        *(float2*)&out[(size_t)ra * TZ + col] =
                            make_float2(acc2[nt][0], acc2[nt][1]);
                        *(float2*)&out[(size_t)(ra + 8) * TZ + col] =
                            make_float2(acc2[nt][2], acc2[nt][3]);
                    }
                }
            }
        }
    }
}

// ---------------- launch ----------------
extern "C" void kernel_launch(void* const* d_in, const int* in_sizes, int n_in,
                              void* d_out, int out_size) {
    const float* z   = (const float*)d_in[0];   // (1,1024,1024,128)
    const float* cc  = (const float*)d_in[1];   // (1,1024,3)
    const float* tdm = (const float*)d_in[2];   // (1,1024,1024)
    // d_in[3] = pair_mask (unused by reference)
    const float* Wz  = (const float*)d_in[4];   // (64,128)
    const float* Wa  = (const float*)d_in[5];   // (64,38)
    const float* Wu  = (const float*)d_in[6];   // (128,64)
    const float* zg  = (const float*)d_in[7];   // (128)
    const float* zb  = (const float*)d_in[8];   // (128)
    const float* vg  = (const float*)d_in[9];   // (64)
    const float* vb  = (const float*)d_in[10];  // (64)
    float* out = (float*)d_out;

    size_t smem_bytes = (size_t)SMEM_FLOATS * sizeof(float);
    cudaFuncSetAttribute(td_kernel, cudaFuncAttributeMaxDynamicSharedMemorySize, (int)smem_bytes);
    td_kernel<<<NBLOCKS, THREADS, smem_bytes>>>(z, cc, tdm, Wz, Wa, Wu, zg, zb, vg, vb, out);
}

// round 16
// speedup vs baseline: 1.5542x; 1.5542x over previous
#include <cuda_runtime.h>
#include <cuda_fp16.h>
#include <cstdint>

typedef uint32_t u32;

#define N_TOK 1024
#define TZ 128
#define TD 64
#define NB 38
#define EPSF 1e-5f
#define TM 128
#define THREADS 512
#define NBLOCKS 152
#define NTILES ((N_TOK * N_TOK) / TM)   // 8192

// strides (4-byte units) — conflict-free fragment access
#define ZSTR 136     // f32; ≡8 mod 32: float2 A-loads conflict-free per half-warp phase
#define VNSTR 36     // u32 half2; ≡4 mod 32: u32 lane pattern 4g+tg distinct
#define W1STR 72     // u32 half2; ≡8 mod 32: lane pattern 8tg+g distinct
#define W2STR 136    // u32 half2; ≡8 mod 32

// smem offsets (4-byte units)
#define ZA0_F 0                         // z f32 buf0: 128*136
#define ZA1_F (TM * ZSTR)               // z f32 buf1
#define VN0_F (2 * TM * ZSTR)           // vn half2 buf0: 128*36
#define VN1_F (VN0_F + TM * VNSTR)      // vn half2 buf1
#define W1H_F (VN1_F + TM * VNSTR)      // W1 half2 [64 kp][72]
#define W2H_F (W1H_F + 64 * W1STR)      // W2 half2 [32 kp][136]
#define WAS_F (W2H_F + 32 * W2STR)      // Wa f32 [bin][d] 38x64
#define S_F   (WAS_F + NB * TD)
#define T_F   (S_F + TD)
#define VG_F  (T_F + TD)
#define VB_F  (VG_F + TD)
#define SMEM_FLOATS (VB_F + TD)         // 55680 * 4B = 222720 B

// ---------------- helpers ----------------
__device__ __forceinline__ u32 packh2(float lo, float hi) {
    half2 h = __floats2half2_rn(lo, hi);      // .x = lo (low 16 bits)
    return *(u32*)&h;
}
__device__ __forceinline__ void cpa16(float* dst, const void* g) {
    u32 a = (u32)__cvta_generic_to_shared(dst);
    asm volatile("cp.async.cg.shared.global [%0], [%1], 16;" :: "r"(a), "l"(g));
}
__device__ __forceinline__ void cpa_commit() { asm volatile("cp.async.commit_group;"); }
__device__ __forceinline__ void cpa_wait0() { asm volatile("cp.async.wait_group 0;" ::: "memory"); }

// streaming store (evict-first; out is write-once)
__device__ __forceinline__ void stcs2(float* p, float x, float y) {
    asm volatile("st.global.cs.v2.f32 [%0], {%1, %2};" :: "l"(p), "f"(x), "f"(y) : "memory");
}

// D += A(16x16,row) * B(16x8,col), fp16 inputs, f32 accum
__device__ __forceinline__ void mma16(float* c, const u32* a, u32 b0, u32 b1) {
    asm volatile(
        "mma.sync.aligned.m16n8k16.row.col.f32.f16.f16.f32 "
        "{%0,%1,%2,%3}, {%4,%5,%6,%7}, {%8,%9}, {%0,%1,%2,%3};"
        : "+f"(c[0]), "+f"(c[1]), "+f"(c[2]), "+f"(c[3])
        : "r"(a[0]), "r"(a[1]), "r"(a[2]), "r"(a[3]), "r"(b0), "r"(b1));
}

// ---------------- main fused kernel ----------------
__global__ __launch_bounds__(THREADS, 1)
void td_kernel(const float* __restrict__ z, const float* __restrict__ cc,
               const float* __restrict__ tdm, const float* __restrict__ Wz,
               const float* __restrict__ Wa, const float* __restrict__ Wu,
               const float* __restrict__ zg, const float* __restrict__ zb,
               const float* __restrict__ vg, const float* __restrict__ vb,
               float* __restrict__ out)
{
    extern __shared__ float smf[];
    u32* smu = (u32*)smf;
    const int t = threadIdx.x;
    const int wid = t >> 5, lane = t & 31;
    const int g = lane >> 2, tg = lane & 3;
    const bool isG1 = (wid < 8);
    const int R1 = (wid & 7) * 16;
    const int t2 = t & 255;

    // ---- prefetch first tile (all 512 threads) ----
    const int tile0 = blockIdx.x;
    {
        const float* src = z + (size_t)tile0 * TM * TZ;
        #pragma unroll
        for (int i = 0; i < 8; i++) {
            int e = i * THREADS + t;            // 0..4095 float4
            cpa16(&smf[ZA0_F + (e >> 5) * ZSTR + (e & 31) * 4], src + e * 4);
        }
        cpa_commit();
    }

    // ---- one-time weight staging ----
    // W1 half2: w1h[kp][n] = {Wz[n][2kp]*zg[2kp], Wz[n][2kp+1]*zg[2kp+1]}
    for (int s = t; s < 64 * TD; s += THREADS) {
        int kp = s >> 6, n = s & 63;
        float lo = Wz[n * TZ + 2 * kp]     * zg[2 * kp];
        float hi = Wz[n * TZ + 2 * kp + 1] * zg[2 * kp + 1];
        smu[W1H_F + kp * W1STR + n] = packh2(lo, hi);
    }
    // W2 half2: w2h[kp][c] = {Wu[c][2kp], Wu[c][2kp+1]}
    for (int s = t; s < 32 * TZ; s += THREADS) {
        int kp = s >> 7, c = s & 127;
        smu[W2H_F + kp * W2STR + c] = packh2(Wu[c * TD + 2 * kp], Wu[c * TD + 2 * kp + 1]);
    }
    for (int s = t; s < NB * TD; s += THREADS) {
        int k = s >> 6, d = s & 63;
        smf[WAS_F + k * TD + d] = Wa[d * NB + k];
    }
    if (t < TD) {
        float S = 0.f, T = 0.f;
        for (int k = 0; k < TZ; k++) {
            S += __half2float(__float2half_rn(Wz[t * TZ + k] * zg[k]));
            T += Wz[t * TZ + k] * zb[k];
        }
        smf[S_F + t] = S; smf[T_F + t] = T;
        smf[VG_F + t] = vg[t]; smf[VB_F + t] = vb[t];
    }

    const int ng1 = (NTILES - 1 - tile0) / NBLOCKS + 1;
    const int it_count = ng1 + 1;        // +1 drain iteration

    int tile = tile0;
    for (int it = 0; it < it_count; it++, tile += NBLOCKS) {
        const int cur = it & 1;
        float* zc   = &smf[cur ? ZA1_F : ZA0_F];       // z(tile)            [G1 in]
        u32* vncur  = &smu[cur ? VN1_F : VN0_F];       // vn(tile)           [G1 out]
        u32* vnprev = &smu[cur ? VN0_F : VN1_F];       // vn(tile-NBLOCKS)   [G2 in]
        float* znxt = &smf[cur ? ZA0_F : ZA1_F];       // z(tile+NBLOCKS)    [prefetch dst]

        cpa_wait0();
        __syncthreads();   // single block barrier per iteration

        if (isG1) {
            if (tile < NTILES) {
                const int base_p = tile * TM;

                // ---- bins + mask (rows R1+g, R1+g+8) ----
                int bin0, bin1;
                float mk0, mk1;
                {
                    const int i0 = base_p >> 10;
                    const int jb = base_p & (N_TOK - 1);
                    const float cx = __ldg(cc + i0 * 3 + 0);
                    const float cy = __ldg(cc + i0 * 3 + 1);
                    const float cz = __ldg(cc + i0 * 3 + 2);
                    #pragma unroll
                    for (int i = 0; i < 2; i++) {
                        const int row = R1 + g + 8 * i;
                        const int j0 = jb + row;
                        float dx = cx - __ldg(cc + j0 * 3 + 0);
                        float dy = cy - __ldg(cc + j0 * 3 + 1);
                        float dz = cz - __ldg(cc + j0 * 3 + 2);
                        float dist = sqrtf(dx * dx + dy * dy + dz * dz);
                        int idx = 0;
                        #pragma unroll
                        for (int k = 0; k < NB - 1; k++) {
                            float b = (float)(3.25 + k * (47.5 / 36.0));
                            idx += (dist > b) ? 1 : 0;
                        }
                        if (i == 0) { bin0 = idx; mk0 = __ldg(tdm + base_p + row); }
                        else        { bin1 = idx; mk1 = __ldg(tdm + base_p + row); }
                    }
                }

                // ---- GEMM1 fp16 (warp tile 16x64, 8 k16-steps) + LN1 stats ----
                float acc[8][4];
                #pragma unroll
                for (int b = 0; b < 8; b++)
                    #pragma unroll
                    for (int cI = 0; cI < 4; cI++) acc[b][cI] = 0.f;
                float s0 = 0.f, q0 = 0.f, s1 = 0.f, q1 = 0.f;

                #pragma unroll
                for (int ks = 0; ks < 8; ks++) {
                    const int k0 = ks * 16;
                    const float* zr = &zc[(R1 + g) * ZSTR + k0 + 2 * tg];
                    float2 p0 = *(const float2*)zr;                      // row g,   k..k+1
                    float2 p2 = *(const float2*)(zr + 8);                // row g,   k+8..k+9
                    float2 p1 = *(const float2*)(zr + 8 * ZSTR);         // row g+8, k..k+1
                    float2 p3 = *(const float2*)(zr + 8 * ZSTR + 8);     // row g+8, k+8..k+9
                    s0 += p0.x + p0.y + p2.x + p2.y;
                    q0 += p0.x * p0.x + p0.y * p0.y + p2.x * p2.x + p2.y * p2.y;
                    s1 += p1.x + p1.y + p3.x + p3.y;
                    q1 += p1.x * p1.x + p1.y * p1.y + p3.x * p3.x + p3.y * p3.y;
                    u32 afr[4];
                    afr[0] = packh2(p0.x, p0.y);
                    afr[1] = packh2(p1.x, p1.y);
                    afr[2] = packh2(p2.x, p2.y);
                    afr[3] = packh2(p3.x, p3.y);
                    const u32* wbase = &smu[W1H_F + (8 * ks + tg) * W1STR + g];
                    #pragma unroll
                    for (int nt = 0; nt < 8; nt++) {
                        u32 b0 = wbase[8 * nt];
                        u32 b1 = wbase[8 * nt + 4 * W1STR];
                        mma16(acc[nt], afr, b0, b1);
                    }
                }

                // LN1 finalize (reduce over tg lanes)
                float m1a, r1a, m1b, r1b;
                {
                    float sa = s0, qa = q0, sb = s1, qb = q1;
                    sa += __shfl_xor_sync(0xffffffffu, sa, 1);
                    qa += __shfl_xor_sync(0xffffffffu, qa, 1);
                    sb += __shfl_xor_sync(0xffffffffu, sb, 1);
                    qb += __shfl_xor_sync(0xffffffffu, qb, 1);
                    sa += __shfl_xor_sync(0xffffffffu, sa, 2);
                    qa += __shfl_xor_sync(0xffffffffu, qa, 2);
                    sb += __shfl_xor_sync(0xffffffffu, sb, 2);
                    qb += __shfl_xor_sync(0xffffffffu, qb, 2);
                    m1a = sa * (1.f / TZ);
                    float va = fmaxf(qa * (1.f / TZ) - m1a * m1a, 0.f);
                    r1a = rsqrtf(va + EPSF);
                    m1b = sb * (1.f / TZ);
                    float vb_ = fmaxf(qb * (1.f / TZ) - m1b * m1b, 0.f);
                    r1b = rsqrtf(vb_ + EPSF);
                }

                // ---- epilogue 1: LN1-fold + bin column + LN2 stats (warp-local) ----
                float s2a = 0.f, q2a = 0.f, s2b = 0.f, q2b = 0.f;
                #pragma unroll
                for (int nt = 0; nt < 8; nt++) {
                    const int col = 8 * nt + 2 * tg;
                    float2 Sv = *(const float2*)&smf[S_F + col];
                    float2 Tv = *(const float2*)&smf[T_F + col];
                    float2 W0 = *(const float2*)&smf[WAS_F + bin0 * TD + col];
                    float2 W1v = *(const float2*)&smf[WAS_F + bin1 * TD + col];
                    float v0 = r1a * (acc[nt][0] - m1a * Sv.x) + Tv.x + mk0 * W0.x;
                    float v1 = r1a * (acc[nt][1] - m1a * Sv.y) + Tv.y + mk0 * W0.y;
                    float v2 = r1b * (acc[nt][2] - m1b * Sv.x) + Tv.x + mk1 * W1v.x;
                    float v3 = r1b * (acc[nt][3] - m1b * Sv.y) + Tv.y + mk1 * W1v.y;
                    acc[nt][0] = v0; acc[nt][1] = v1; acc[nt][2] = v2; acc[nt][3] = v3;
                    s2a += v0 + v1;  q2a += v0 * v0 + v1 * v1;
                    s2b += v2 + v3;  q2b += v2 * v2 + v3 * v3;
                }
                s2a += __shfl_xor_sync(0xffffffffu, s2a, 1);
                q2a += __shfl_xor_sync(0xffffffffu, q2a, 1);
                s2b += __shfl_xor_sync(0xffffffffu, s2b, 1);
                q2b += __shfl_xor_sync(0xffffffffu, q2b, 1);
                s2a += __shfl_xor_sync(0xffffffffu, s2a, 2);
                q2a += __shfl_xor_sync(0xffffffffu, q2a, 2);
                s2b += __shfl_xor_sync(0xffffffffu, s2b, 2);
                q2b += __shfl_xor_sync(0xffffffffu, q2b, 2);
                float m2a = s2a * (1.f / TD);
                float vva = fmaxf(q2a * (1.f / TD) - m2a * m2a, 0.f);
                float sca = 2.f * rsqrtf(4.f * vva + EPSF);    // exact v+v doubling
                float m2b = s2b * (1.f / TD);
                float vvb = fmaxf(q2b * (1.f / TD) - m2b * m2b, 0.f);
                float scb = 2.f * rsqrtf(4.f * vvb + EPSF);

                // ---- normalize + relu -> vn (half2 packed along d) ----
                #pragma unroll
                for (int nt = 0; nt < 8; nt++) {
                    const int col = 8 * nt + 2 * tg;
                    float2 gv = *(const float2*)&smf[VG_F + col];
                    float2 bv = *(const float2*)&smf[VB_F + col];
                    float a0 = fmaxf(fmaf((acc[nt][0] - m2a) * sca, gv.x, bv.x), 0.f);
                    float a1 = fmaxf(fmaf((acc[nt][1] - m2a) * sca, gv.y, bv.y), 0.f);
                    float b0 = fmaxf(fmaf((acc[nt][2] - m2b) * scb, gv.x, bv.x), 0.f);
                    float b1 = fmaxf(fmaf((acc[nt][3] - m2b) * scb, gv.y, bv.y), 0.f);
                    const int kp = 4 * nt + tg;                  // d-pair index
                    vncur[(R1 + g) * VNSTR + kp]     = packh2(a0, a1);
                    vncur[(R1 + g + 8) * VNSTR + kp] = packh2(b0, b1);
                }
            }
        } else {
            // ---- prefetch next z first (max overlap), then GEMM2 ----
            const int tile_next = tile + NBLOCKS;
            if (tile_next < NTILES) {
                const float* src = z + (size_t)tile_next * TM * TZ;
                #pragma unroll
                for (int i = 0; i < 16; i++) {
                    int e = i * 256 + t2;
                    cpa16(&znxt[(e >> 5) * ZSTR + (e & 31) * 4], src + e * 4);
                }
                cpa_commit();
            }

            // ---- GEMM2 fp16 (warp tile 16x128, 4 k16-steps) on vn(tile-NBLOCKS) ----
            if (it > 0) {
                const int base_p = (tile - NBLOCKS) * TM;
                float acc2[16][4];
                #pragma unroll
                for (int b = 0; b < 16; b++)
                    #pragma unroll
                    for (int cI = 0; cI < 4; cI++) acc2[b][cI] = 0.f;

                #pragma unroll
                for (int ks = 0; ks < 4; ks++) {
                    const u32* vr = &vnprev[(R1 + g) * VNSTR + 8 * ks + tg];
                    u32 afr[4];
                    afr[0] = vr[0];                    // row g,   d-pair kp
                    afr[1] = vr[8 * VNSTR];            // row g+8, kp
                    afr[2] = vr[4];                    // row g,   kp+4
                    afr[3] = vr[8 * VNSTR + 4];        // row g+8, kp+4
                    const u32* wbase = &smu[W2H_F + (8 * ks + tg) * W2STR + g];
                    #pragma unroll
                    for (int nt = 0; nt < 16; nt++) {
                        u32 b0 = wbase[8 * nt];
                        u32 b1 = wbase[8 * nt + 4 * W2STR];
                        mma16(acc2[nt], afr, b0, b1);
                    }
                }
                {
                    const int ra = base_p + R1 + g;
                    #pragma unroll
                    for (int nt = 0; nt < 16; nt++) {
                        const int col = 8 * nt + 2 * tg;
                        stcs2(&out[(size_t)ra * TZ + col], acc2[nt][0], acc2[nt][1]);
                        stcs2(&out[(size_t)(ra + 8) * TZ + col], acc2[nt][2], acc2[nt][3]);
                    }
                }
            }
        }
    }
}

// ---------------- launch ----------------
extern "C" void kernel_launch(void* const* d_in, const int* in_sizes, int n_in,
                              void* d_out, int out_size) {
    const float* z   = (const float*)d_in[0];   // (1,1024,1024,128)
    const float* cc  = (const float*)d_in[1];   // (1,1024,3)
    const float* tdm = (const float*)d_in[2];   // (1,1024,1024)
    // d_in[3] = pair_mask (unused by reference)
    const float* Wz  = (const float*)d_in[4];   // (64,128)
    const float* Wa  = (const float*)d_in[5];   // (64,38)
    const float* Wu  = (const float*)d_in[6];   // (128,64)
    const float* zg  = (const float*)d_in[7];   // (128)
    const float* zb  = (const float*)d_in[8];   // (128)
    const float* vg  = (const float*)d_in[9];   // (64)
    const float* vb  = (const float*)d_in[10];  // (64)
    float* out = (float*)d_out;

    size_t smem_bytes = (size_t)SMEM_FLOATS * sizeof(float);
    cudaFuncSetAttribute(td_kernel, cudaFuncAttributeMaxDynamicSharedMemorySize, (int)smem_bytes);
    td_kernel<<<NBLOCKS, THREADS, smem_bytes>>>(z, cc, tdm, Wz, Wa, Wu, zg, zb, vg, vb, out);
}

// round 17
// speedup vs baseline: 1.5718x; 1.0114x over previous
#include <cuda_runtime.h>
#include <cuda_fp16.h>
#include <cstdint>

typedef uint32_t u32;

#define N_TOK 1024
#define TZ 128
#define TD 64
#define NB 38
#define EPSF 1e-5f
#define TM 128
#define THREADS 512
#define NBLOCKS 152
#define NTILES ((N_TOK * N_TOK) / TM)   // 8192

// strides (4-byte units) — conflict-free fragment access
#define ZSTR 136     // f32; ≡8 mod 32
#define VNSTR 36     // u32 half2; ≡4 mod 32
#define W1STR 72     // u32 half2; ≡8 mod 32
#define W2STR 136    // u32 half2; ≡8 mod 32

// smem offsets (4-byte units)
#define ZA0_F 0                         // z f32 buf0: 128*136
#define ZA1_F (TM * ZSTR)               // z f32 buf1
#define VN0_F (2 * TM * ZSTR)           // vn half2 buf0: 128*36
#define VN1_F (VN0_F + TM * VNSTR)      // vn half2 buf1
#define W1H_F (VN1_F + TM * VNSTR)      // W1 half2 [64 kp][72]
#define W2H_F (W1H_F + 64 * W1STR)      // W2 half2 [32 kp][136]
#define WAS_F (W2H_F + 32 * W2STR)      // Wa f32 [bin][d] 38x64
#define S_F   (WAS_F + NB * TD)
#define T_F   (S_F + TD)
#define VG_F  (T_F + TD)
#define VB_F  (VG_F + TD)
#define SMEM_FLOATS (VB_F + TD)         // 55680 * 4B = 222720 B

// ---------------- helpers ----------------
__device__ __forceinline__ u32 packh2(float lo, float hi) {
    half2 h = __floats2half2_rn(lo, hi);      // .x = lo (low 16 bits)
    return *(u32*)&h;
}
__device__ __forceinline__ void cpa16(float* dst, const void* g) {
    u32 a = (u32)__cvta_generic_to_shared(dst);
    asm volatile("cp.async.cg.shared.global [%0], [%1], 16;" :: "r"(a), "l"(g));
}
__device__ __forceinline__ void cpa_commit() { asm volatile("cp.async.commit_group;"); }
__device__ __forceinline__ void cpa_wait0() { asm volatile("cp.async.wait_group 0;" ::: "memory"); }

// streaming store (evict-first; out is write-once)
__device__ __forceinline__ void stcs2(float* p, float x, float y) {
    asm volatile("st.global.cs.v2.f32 [%0], {%1, %2};" :: "l"(p), "f"(x), "f"(y) : "memory");
}

// D += A(16x16,row) * B(16x8,col), fp16 inputs, f32 accum
__device__ __forceinline__ void mma16(float* c, const u32* a, u32 b0, u32 b1) {
    asm volatile(
        "mma.sync.aligned.m16n8k16.row.col.f32.f16.f16.f32 "
        "{%0,%1,%2,%3}, {%4,%5,%6,%7}, {%8,%9}, {%0,%1,%2,%3};"
        : "+f"(c[0]), "+f"(c[1]), "+f"(c[2]), "+f"(c[3])
        : "r"(a[0]), "r"(a[1]), "r"(a[2]), "r"(a[3]), "r"(b0), "r"(b1));
}

// ---------------- main fused kernel ----------------
__global__ __launch_bounds__(THREADS, 1)
void td_kernel(const float* __restrict__ z, const float* __restrict__ cc,
               const float* __restrict__ tdm, const float* __restrict__ Wz,
               const float* __restrict__ Wa, const float* __restrict__ Wu,
               const float* __restrict__ zg, const float* __restrict__ zb,
               const float* __restrict__ vg, const float* __restrict__ vb,
               float* __restrict__ out)
{
    extern __shared__ float smf[];
    u32* smu = (u32*)smf;
    const int t = threadIdx.x;
    const int wid = t >> 5, lane = t & 31;
    const int g = lane >> 2, tg = lane & 3;
    const bool isG1 = (wid < 8);
    const int R1 = (wid & 7) * 16;          // G1: 16 rows per warp
    const int R2 = (wid & 3) * 32;          // G2: 32 rows per warp
    const int C2 = ((wid >> 2) & 1) * 64;   // G2: N-half per warp
    const int t2 = t & 255;

    // ---- prefetch first tile (all 512 threads) ----
    const int tile0 = blockIdx.x;
    {
        const float* src = z + (size_t)tile0 * TM * TZ;
        #pragma unroll
        for (int i = 0; i < 8; i++) {
            int e = i * THREADS + t;            // 0..4095 float4
            cpa16(&smf[ZA0_F + (e >> 5) * ZSTR + (e & 31) * 4], src + e * 4);
        }
        cpa_commit();
    }

    // ---- one-time weight staging ----
    // W1 half2: w1h[kp][n] = {Wz[n][2kp]*zg[2kp], Wz[n][2kp+1]*zg[2kp+1]}
    for (int s = t; s < 64 * TD; s += THREADS) {
        int kp = s >> 6, n = s & 63;
        float lo = Wz[n * TZ + 2 * kp]     * zg[2 * kp];
        float hi = Wz[n * TZ + 2 * kp + 1] * zg[2 * kp + 1];
        smu[W1H_F + kp * W1STR + n] = packh2(lo, hi);
    }
    // W2 half2: w2h[kp][c] = {Wu[c][2kp], Wu[c][2kp+1]}
    for (int s = t; s < 32 * TZ; s += THREADS) {
        int kp = s >> 7, c = s & 127;
        smu[W2H_F + kp * W2STR + c] = packh2(Wu[c * TD + 2 * kp], Wu[c * TD + 2 * kp + 1]);
    }
    for (int s = t; s < NB * TD; s += THREADS) {
        int k = s >> 6, d = s & 63;
        smf[WAS_F + k * TD + d] = Wa[d * NB + k];
    }
    if (t < TD) {
        float S = 0.f, T = 0.f;
        for (int k = 0; k < TZ; k++) {
            S += __half2float(__float2half_rn(Wz[t * TZ + k] * zg[k]));
            T += Wz[t * TZ + k] * zb[k];
        }
        smf[S_F + t] = S; smf[T_F + t] = T;
        smf[VG_F + t] = vg[t]; smf[VB_F + t] = vb[t];
    }

    const int ng1 = (NTILES - 1 - tile0) / NBLOCKS + 1;
    const int it_count = ng1 + 1;        // +1 drain iteration

    int tile = tile0;
    for (int it = 0; it < it_count; it++, tile += NBLOCKS) {
        const int cur = it & 1;
        float* zc   = &smf[cur ? ZA1_F : ZA0_F];       // z(tile)            [G1 in]
        u32* vncur  = &smu[cur ? VN1_F : VN0_F];       // vn(tile)           [G1 out]
        u32* vnprev = &smu[cur ? VN0_F : VN1_F];       // vn(tile-NBLOCKS)   [G2 in]
        float* znxt = &smf[cur ? ZA0_F : ZA1_F];       // z(tile+NBLOCKS)    [prefetch dst]

        cpa_wait0();
        __syncthreads();   // single block barrier per iteration

        if (isG1) {
            if (tile < NTILES) {
                const int base_p = tile * TM;

                // ---- bins + mask (rows R1+g, R1+g+8) ----
                int bin0, bin1;
                float mk0, mk1;
                {
                    const int i0 = base_p >> 10;
                    const int jb = base_p & (N_TOK - 1);
                    const float cx = __ldg(cc + i0 * 3 + 0);
                    const float cy = __ldg(cc + i0 * 3 + 1);
                    const float cz = __ldg(cc + i0 * 3 + 2);
                    #pragma unroll
                    for (int i = 0; i < 2; i++) {
                        const int row = R1 + g + 8 * i;
                        const int j0 = jb + row;
                        float dx = cx - __ldg(cc + j0 * 3 + 0);
                        float dy = cy - __ldg(cc + j0 * 3 + 1);
                        float dz = cz - __ldg(cc + j0 * 3 + 2);
                        float dist = sqrtf(dx * dx + dy * dy + dz * dz);
                        int idx = 0;
                        #pragma unroll
                        for (int k = 0; k < NB - 1; k++) {
                            float b = (float)(3.25 + k * (47.5 / 36.0));
                            idx += (dist > b) ? 1 : 0;
                        }
                        if (i == 0) { bin0 = idx; mk0 = __ldg(tdm + base_p + row); }
                        else        { bin1 = idx; mk1 = __ldg(tdm + base_p + row); }
                    }
                }

                // ---- GEMM1 fp16 (warp tile 16x64, 8 k16-steps) + LN1 stats ----
                float acc[8][4];
                #pragma unroll
                for (int b = 0; b < 8; b++)
                    #pragma unroll
                    for (int cI = 0; cI < 4; cI++) acc[b][cI] = 0.f;
                float s0 = 0.f, q0 = 0.f, s1 = 0.f, q1 = 0.f;

                #pragma unroll
                for (int ks = 0; ks < 8; ks++) {
                    const int k0 = ks * 16;
                    const float* zr = &zc[(R1 + g) * ZSTR + k0 + 2 * tg];
                    float2 p0 = *(const float2*)zr;                      // row g,   k..k+1
                    float2 p2 = *(const float2*)(zr + 8);                // row g,   k+8..k+9
                    float2 p1 = *(const float2*)(zr + 8 * ZSTR);         // row g+8, k..k+1
                    float2 p3 = *(const float2*)(zr + 8 * ZSTR + 8);     // row g+8, k+8..k+9
                    s0 += p0.x + p0.y + p2.x + p2.y;
                    q0 += p0.x * p0.x + p0.y * p0.y + p2.x * p2.x + p2.y * p2.y;
                    s1 += p1.x + p1.y + p3.x + p3.y;
                    q1 += p1.x * p1.x + p1.y * p1.y + p3.x * p3.x + p3.y * p3.y;
                    u32 afr[4];
                    afr[0] = packh2(p0.x, p0.y);
                    afr[1] = packh2(p1.x, p1.y);
                    afr[2] = packh2(p2.x, p2.y);
                    afr[3] = packh2(p3.x, p3.y);
                    const u32* wbase = &smu[W1H_F + (8 * ks + tg) * W1STR + g];
                    #pragma unroll
                    for (int nt = 0; nt < 8; nt++) {
                        u32 b0 = wbase[8 * nt];
                        u32 b1 = wbase[8 * nt + 4 * W1STR];
                        mma16(acc[nt], afr, b0, b1);
                    }
                }

                // LN1 finalize (reduce over tg lanes)
                float m1a, r1a, m1b, r1b;
                {
                    float sa = s0, qa = q0, sb = s1, qb = q1;
                    sa += __shfl_xor_sync(0xffffffffu, sa, 1);
                    qa += __shfl_xor_sync(0xffffffffu, qa, 1);
                    sb += __shfl_xor_sync(0xffffffffu, sb, 1);
                    qb += __shfl_xor_sync(0xffffffffu, qb, 1);
                    sa += __shfl_xor_sync(0xffffffffu, sa, 2);
                    qa += __shfl_xor_sync(0xffffffffu, qa, 2);
                    sb += __shfl_xor_sync(0xffffffffu, sb, 2);
                    qb += __shfl_xor_sync(0xffffffffu, qb, 2);
                    m1a = sa * (1.f / TZ);
                    float va = fmaxf(qa * (1.f / TZ) - m1a * m1a, 0.f);
                    r1a = rsqrtf(va + EPSF);
                    m1b = sb * (1.f / TZ);
                    float vb_ = fmaxf(qb * (1.f / TZ) - m1b * m1b, 0.f);
                    r1b = rsqrtf(vb_ + EPSF);
                }

                // ---- epilogue 1: LN1-fold + bin column + LN2 stats (warp-local) ----
                float s2a = 0.f, q2a = 0.f, s2b = 0.f, q2b = 0.f;
                #pragma unroll
                for (int nt = 0; nt < 8; nt++) {
                    const int col = 8 * nt + 2 * tg;
                    float2 Sv = *(const float2*)&smf[S_F + col];
                    float2 Tv = *(const float2*)&smf[T_F + col];
                    float2 W0 = *(const float2*)&smf[WAS_F + bin0 * TD + col];
                    float2 W1v = *(const float2*)&smf[WAS_F + bin1 * TD + col];
                    float v0 = r1a * (acc[nt][0] - m1a * Sv.x) + Tv.x + mk0 * W0.x;
                    float v1 = r1a * (acc[nt][1] - m1a * Sv.y) + Tv.y + mk0 * W0.y;
                    float v2 = r1b * (acc[nt][2] - m1b * Sv.x) + Tv.x + mk1 * W1v.x;
                    float v3 = r1b * (acc[nt][3] - m1b * Sv.y) + Tv.y + mk1 * W1v.y;
                    acc[nt][0] = v0; acc[nt][1] = v1; acc[nt][2] = v2; acc[nt][3] = v3;
                    s2a += v0 + v1;  q2a += v0 * v0 + v1 * v1;
                    s2b += v2 + v3;  q2b += v2 * v2 + v3 * v3;
                }
                s2a += __shfl_xor_sync(0xffffffffu, s2a, 1);
                q2a += __shfl_xor_sync(0xffffffffu, q2a, 1);
                s2b += __shfl_xor_sync(0xffffffffu, s2b, 1);
                q2b += __shfl_xor_sync(0xffffffffu, q2b, 1);
                s2a += __shfl_xor_sync(0xffffffffu, s2a, 2);
                q2a += __shfl_xor_sync(0xffffffffu, q2a, 2);
                s2b += __shfl_xor_sync(0xffffffffu, s2b, 2);
                q2b += __shfl_xor_sync(0xffffffffu, q2b, 2);
                float m2a = s2a * (1.f / TD);
                float vva = fmaxf(q2a * (1.f / TD) - m2a * m2a, 0.f);
                float sca = 2.f * rsqrtf(4.f * vva + EPSF);    // exact v+v doubling
                float m2b = s2b * (1.f / TD);
                float vvb = fmaxf(q2b * (1.f / TD) - m2b * m2b, 0.f);
                float scb = 2.f * rsqrtf(4.f * vvb + EPSF);

                // ---- normalize + relu -> vn (half2 packed along d) ----
                #pragma unroll
                for (int nt = 0; nt < 8; nt++) {
                    const int col = 8 * nt + 2 * tg;
                    float2 gv = *(const float2*)&smf[VG_F + col];
                    float2 bv = *(const float2*)&smf[VB_F + col];
                    float a0 = fmaxf(fmaf((acc[nt][0] - m2a) * sca, gv.x, bv.x), 0.f);
                    float a1 = fmaxf(fmaf((acc[nt][1] - m2a) * sca, gv.y, bv.y), 0.f);
                    float b0 = fmaxf(fmaf((acc[nt][2] - m2b) * scb, gv.x, bv.x), 0.f);
                    float b1 = fmaxf(fmaf((acc[nt][3] - m2b) * scb, gv.y, bv.y), 0.f);
                    const int kp = 4 * nt + tg;                  // d-pair index
                    vncur[(R1 + g) * VNSTR + kp]     = packh2(a0, a1);
                    vncur[(R1 + g + 8) * VNSTR + kp] = packh2(b0, b1);
                }
            }
        } else {
            // ---- prefetch next z first (max overlap), then GEMM2 ----
            const int tile_next = tile + NBLOCKS;
            if (tile_next < NTILES) {
                const float* src = z + (size_t)tile_next * TM * TZ;
                #pragma unroll
                for (int i = 0; i < 16; i++) {
                    int e = i * 256 + t2;
                    cpa16(&znxt[(e >> 5) * ZSTR + (e & 31) * 4], src + e * 4);
                }
                cpa_commit();
            }

            // ---- GEMM2 fp16 (warp tile 32x64: M32 x N-half) on vn(tile-NBLOCKS) ----
            if (it > 0) {
                const int base_p = (tile - NBLOCKS) * TM;
                float acc2[2][8][4];
                #pragma unroll
                for (int a = 0; a < 2; a++)
                    #pragma unroll
                    for (int b = 0; b < 8; b++)
                        #pragma unroll
                        for (int cI = 0; cI < 4; cI++) acc2[a][b][cI] = 0.f;

                #pragma unroll
                for (int ks = 0; ks < 4; ks++) {
                    u32 afr[2][4];
                    #pragma unroll
                    for (int rt = 0; rt < 2; rt++) {
                        const u32* vr = &vnprev[(R2 + 16 * rt + g) * VNSTR + 8 * ks + tg];
                        afr[rt][0] = vr[0];                    // row +g,   d-pair kp
                        afr[rt][1] = vr[8 * VNSTR];            // row +g+8, kp
                        afr[rt][2] = vr[4];                    // row +g,   kp+4
                        afr[rt][3] = vr[8 * VNSTR + 4];        // row +g+8, kp+4
                    }
                    const u32* wbase = &smu[W2H_F + (8 * ks + tg) * W2STR + C2 + g];
                    #pragma unroll
                    for (int nt = 0; nt < 8; nt++) {
                        u32 b0 = wbase[8 * nt];
                        u32 b1 = wbase[8 * nt + 4 * W2STR];
                        mma16(acc2[0][nt], afr[0], b0, b1);
                        mma16(acc2[1][nt], afr[1], b0, b1);
                    }
                }
                #pragma unroll
                for (int rt = 0; rt < 2; rt++) {
                    const int ra = base_p + R2 + 16 * rt + g;
                    #pragma unroll
                    for (int nt = 0; nt < 8; nt++) {
                        const int col = C2 + 8 * nt + 2 * tg;
                        stcs2(&out[(size_t)ra * TZ + col], acc2[rt][nt][0], acc2[rt][nt][1]);
                        stcs2(&out[(size_t)(ra + 8) * TZ + col], acc2[rt][nt][2], acc2[rt][nt][3]);
                    }
                }
            }
        }
    }
}

// ---------------- launch ----------------
extern "C" void kernel_launch(void* const* d_in, const int* in_sizes, int n_in,
                              void* d_out, int out_size) {
    const float* z   = (const float*)d_in[0];   // (1,1024,1024,128)
    const float* cc  = (const float*)d_in[1];   // (1,1024,3)
    const float* tdm = (const float*)d_in[2];   // (1,1024,1024)
    // d_in[3] = pair_mask (unused by reference)
    const float* Wz  = (const float*)d_in[4];   // (64,128)
    const float* Wa  = (const float*)d_in[5];   // (64,38)
    const float* Wu  = (const float*)d_in[6];   // (128,64)
    const float* zg  = (const float*)d_in[7];   // (128)
    const float* zb  = (const float*)d_in[8];   // (128)
    const float* vg  = (const float*)d_in[9];   // (64)
    const float* vb  = (const float*)d_in[10];  // (64)
    float* out = (float*)d_out;

    size_t smem_bytes = (size_t)SMEM_FLOATS * sizeof(float);
    cudaFuncSetAttribute(td_kernel, cudaFuncAttributeMaxDynamicSharedMemorySize, (int)smem_bytes);
    td_kernel<<<NBLOCKS, THREADS, smem_bytes>>>(z, cc, tdm, Wz, Wa, Wu, zg, zb, vg, vb, out);
}